// round 4
// baseline (speedup 1.0000x reference)
#include <cuda_runtime.h>

#define NB   64
#define N    256
#define ND   511          // number of anti-diagonals (2N-1)
#define BIGV 1e10f

// Scratch (device globals; no allocations allowed).
// Diag-major layout: X[b][d][j] = cell (i=d-j, j) of batch b.
__device__ float g_Dd[NB * ND * N];   // sheared input costs
__device__ float g_Wl[NB * ND * N];   // softmin weight w_left  per cell
__device__ float g_Wd[NB * ND * N];   // softmin weight w_diag  per cell
__device__ float g_Wu[NB * ND * N];   // softmin weight w_up    per cell
__device__ float g_Ed[NB * ND * N];   // per-batch E
__device__ float g_Es[ND * N];        // batch-mean E (diag-major)

// ---------------------------------------------------------------------------
// Shear: row-major D -> diag-major g_Dd, coalesced both ways via smem tiles.
// grid (8,8,NB), block (32,8)
// ---------------------------------------------------------------------------
__global__ void shear_kernel(const float* __restrict__ D) {
    __shared__ float s[32][33];
    const int b  = blockIdx.z;
    const int i0 = blockIdx.y * 32;
    const int j0 = blockIdx.x * 32;
    const int tx = threadIdx.x, ty = threadIdx.y;

    const float* Db = D + (size_t)b * N * N;
    #pragma unroll
    for (int r = ty; r < 32; r += 8)
        s[r][tx] = Db[(i0 + r) * N + j0 + tx];
    __syncthreads();

    float* out = g_Dd + (size_t)b * ND * N;
    for (int dd = ty; dd < 63; dd += 8) {
        int r = dd - tx;                      // local row index
        if (r >= 0 && r < 32)
            out[(i0 + j0 + dd) * N + (j0 + tx)] = s[r][tx];
    }
}

// ---------------------------------------------------------------------------
// Fused forward + backward DP. One CTA per batch element, thread j = column j.
//
// Forward mirrors the reference's exact fp32 op sequence (this is what keeps
// rel_err down — the recursion amplifies formulation differences by 1/gamma):
//   z_k  = (-v_k) / 0.01f            (IEEE div, as XLA emits for -vals/gamma)
//   zmax = max3(z)
//   s    = (exp(zl-zmax) + exp(zd-zmax)) + exp(zu-zmax)   (libdevice expf)
//   lse  = log(s) + zmax                                  (libdevice logf)
//   minv = (-0.01f) * lse
//   R    = th + minv
//   w_k  = exp(z_k - lse)
// _rn intrinsics prevent ptxas FMA-contraction from perturbing the trajectory.
//
// Backward: E[i,j] = Wl(i,j+1)E(i,j+1) + Wd(i+1,j+1)E(i+1,j+1) + Wu(i+1,j)E(i+1,j)
// (linear, not error-amplifying).
// ---------------------------------------------------------------------------
__global__ __launch_bounds__(256) void dp_kernel() {
    __shared__ float sb[10][N];

    const int b = blockIdx.x;
    const size_t base = (size_t)b * ND * N;
    const float* __restrict__ Dd = g_Dd + base;
    float* __restrict__ Wl = g_Wl + base;
    float* __restrict__ Wd = g_Wd + base;
    float* __restrict__ Wu = g_Wu + base;
    float* __restrict__ Ed = g_Ed + base;

    const int j = threadIdx.x;
    const bool jgt0 = (j > 0);
    const bool jlt  = (j < N - 1);

    // ---------------- forward ----------------
    {
        float *rcur = sb[0], *rp1 = sb[1], *rp2 = sb[2];
        float th = Dd[j];                              // prefetch d=0
        for (int d = 0; d < ND; ++d) {
            float th_next = 0.0f;                      // prefetch next diagonal
            if (d + 1 < ND) th_next = Dd[(d + 1) * N + j];

            const int i = d - j;
            if ((unsigned)i < (unsigned)N) {
                const float vl = jgt0    ? rp1[j - 1] : BIGV;          // R[i][j-1]
                const float vu = (i > 0) ? rp1[j]     : BIGV;          // R[i-1][j]
                float vd;                                              // R[i-1][j-1]
                if (i > 0 && jgt0)       vd = rp2[j - 1];
                else                     vd = (i == 0 && j == 0) ? 0.0f : BIGV;

                const float zl = __fdiv_rn(-vl, 0.01f);
                const float zd = __fdiv_rn(-vd, 0.01f);
                const float zu = __fdiv_rn(-vu, 0.01f);
                const float zmax = fmaxf(fmaxf(zl, zd), zu);
                const float el = expf(__fsub_rn(zl, zmax));
                const float ed = expf(__fsub_rn(zd, zmax));
                const float eu = expf(__fsub_rn(zu, zmax));
                const float ssum = __fadd_rn(__fadd_rn(el, ed), eu);
                const float lse  = __fadd_rn(logf(ssum), zmax);
                const float minv = __fmul_rn(-0.01f, lse);
                const float R    = __fadd_rn(th, minv);

                Wl[d * N + j] = expf(__fsub_rn(zl, lse));
                Wd[d * N + j] = expf(__fsub_rn(zd, lse));
                Wu[d * N + j] = expf(__fsub_rn(zu, lse));
                rcur[j] = R;
            }
            __syncthreads();
            th = th_next;
            float* t = rp2; rp2 = rp1; rp1 = rcur; rcur = t;
        }
    }

    // ---------------- backward ----------------
    {
        float *ecur = sb[0], *ep1 = sb[1], *ep2 = sb[2];
        float *qlc  = sb[3], *qlp = sb[4];                  // w_left  (cur, d+1)
        float *quc  = sb[5], *qup = sb[6];                  // w_up    (cur, d+1)
        float *qdc  = sb[7], *qdp1 = sb[8], *qdp2 = sb[9];  // w_diag  (cur, d+1, d+2)

        float wl = Wl[(ND - 1) * N + j];                    // prefetch d=ND-1
        float wd = Wd[(ND - 1) * N + j];
        float wu = Wu[(ND - 1) * N + j];
        for (int d = ND - 1; d >= 0; --d) {
            float wl_n = 0.0f, wd_n = 0.0f, wu_n = 0.0f;
            if (d > 0) {
                wl_n = Wl[(d - 1) * N + j];
                wd_n = Wd[(d - 1) * N + j];
                wu_n = Wu[(d - 1) * N + j];
            }

            const int i = d - j;
            if ((unsigned)i < (unsigned)N) {
                float e;
                if (i == N - 1 && j == N - 1) {
                    e = 1.0f;
                } else {
                    float t0 = 0.0f, t1 = 0.0f, t2 = 0.0f;
                    if (jlt)                       // from (i, j+1)  @ diag d+1
                        t0 = __fmul_rn(qlp[j + 1], ep1[j + 1]);
                    if (i < N - 1) {
                        if (jlt)                   // from (i+1,j+1) @ diag d+2
                            t1 = __fmul_rn(qdp2[j + 1], ep2[j + 1]);
                        t2 = __fmul_rn(qup[j], ep1[j]);   // from (i+1, j) @ d+1
                    }
                    e = __fadd_rn(__fadd_rn(t0, t1), t2);
                }
                Ed[d * N + j] = e;
                ecur[j] = e;
                qlc[j] = wl;
                quc[j] = wu;
                qdc[j] = wd;
            }
            __syncthreads();
            wl = wl_n; wd = wd_n; wu = wu_n;
            float* t;
            t = ep2;  ep2  = ep1;  ep1 = ecur; ecur = t;
            t = qlp;  qlp  = qlc;  qlc = t;
            t = qup;  qup  = quc;  quc = t;
            t = qdp2; qdp2 = qdp1; qdp1 = qdc; qdc = t;
        }
    }
}

// ---------------------------------------------------------------------------
// Batch-mean over b (coalesced), still diag-major.
// ---------------------------------------------------------------------------
__global__ void reduce_kernel() {
    const int idx = blockIdx.x * blockDim.x + threadIdx.x;   // < ND*N
    float s = 0.0f;
    #pragma unroll 4
    for (int b = 0; b < NB; ++b)
        s += g_Ed[(size_t)b * ND * N + idx];
    g_Es[idx] = s * (1.0f / NB);
}

// ---------------------------------------------------------------------------
// Un-shear diag-major mean into the row-major output.
// ---------------------------------------------------------------------------
__global__ void gather_kernel(float* __restrict__ out) {
    const int idx = blockIdx.x * blockDim.x + threadIdx.x;   // < N*N
    const int i = idx >> 8;
    const int j = idx & (N - 1);
    out[idx] = g_Es[(i + j) * N + j];
}

// ---------------------------------------------------------------------------
extern "C" void kernel_launch(void* const* d_in, const int* in_sizes, int n_in,
                              void* d_out, int out_size) {
    const float* D = (const float*)d_in[0];
    float* out = (float*)d_out;

    shear_kernel<<<dim3(8, 8, NB), dim3(32, 8)>>>(D);
    dp_kernel<<<NB, 256>>>();
    reduce_kernel<<<ND, 256>>>();
    gather_kernel<<<(N * N) / 256, 256>>>(out);
}